// round 2
// baseline (speedup 1.0000x reference)
#include <cuda_runtime.h>
#include <math_constants.h>
#include <cstdint>

// Problem constants
#define BATCH   8
#define TSEQ    1024
#define CDIM    768
#define NHEAD   12
#define DHEAD   64
#define QKVN    (3 * CDIM)   // 2304

// Scratch (device globals: allocation-free rule)
__device__ float g_q[(size_t)BATCH * NHEAD * TSEQ * DHEAD];
__device__ float g_k[(size_t)BATCH * NHEAD * TSEQ * DHEAD];
__device__ float g_v[(size_t)BATCH * NHEAD * TSEQ * DHEAD];
__device__ float g_y[(size_t)BATCH * TSEQ * CDIM];

__device__ __forceinline__ uint32_t f2tf32(float f) {
    uint32_t r;
    asm("cvt.rna.tf32.f32 %0, %1;" : "=r"(r) : "f"(f));
    return r;
}

__device__ __forceinline__ void mma_tf32(float c[4], const uint32_t a[4], const uint32_t b[2]) {
    asm volatile(
        "mma.sync.aligned.m16n8k8.row.col.f32.tf32.tf32.f32 "
        "{%0,%1,%2,%3}, {%4,%5,%6,%7}, {%8,%9}, {%0,%1,%2,%3};"
        : "+f"(c[0]), "+f"(c[1]), "+f"(c[2]), "+f"(c[3])
        : "r"(a[0]), "r"(a[1]), "r"(a[2]), "r"(a[3]),
          "r"(b[0]), "r"(b[1]));
}

// ---------------------------------------------------------------------------
// tf32 tensor-core GEMM: C[M,N] = A[M,K]*B[K,N] + bias, fused epilogue.
// MODE 0 (QKV): A = x, B = w_attn. Splits q/k/v, scales q, folds shifted
//               rel_emb into k, writes [B,H,T,D] buffers.
// MODE 1 (PROJ): A = g_y, B = w_proj -> out.
// BM=BN=128, BK=16, 256 threads (8 warps, 2x4), warp tile 64x32,
// mma m16n8k8 (4x4 tiles/warp). Smem row stride 136 (==8 mod 32,
// conflict-free fragment loads).
// ---------------------------------------------------------------------------
template <int MODE>
__global__ __launch_bounds__(256)
void gemm_kernel(const float* __restrict__ A,
                 const float* __restrict__ B,
                 const float* __restrict__ bias,
                 const float* __restrict__ rel_emb,
                 float* __restrict__ out,
                 int N)
{
    const int BM = 128, BK = 16;
    const int K = CDIM;
    const int LDS_ = 136;   // smem row stride in floats (136 % 32 == 8)

    __shared__ __align__(16) float As[BK][LDS_];   // [k][m]
    __shared__ __align__(16) float Bs[BK][LDS_];   // [k][n]

    const int tid   = threadIdx.x;
    const int warp  = tid >> 5;
    const int lane  = tid & 31;
    const int group = lane >> 2;   // 0..7
    const int tig   = lane & 3;    // 0..3
    const int warp_m = warp >> 2;  // 0..1 -> m offset *64
    const int warp_n = warp & 3;   // 0..3 -> n offset *32
    const int m0 = blockIdx.y * BM;
    const int n0 = blockIdx.x * BM;

    const float* Ap = (MODE == 0) ? A : g_y;

    float acc[4][4][4];
#pragma unroll
    for (int i = 0; i < 4; i++)
#pragma unroll
        for (int j = 0; j < 4; j++)
#pragma unroll
            for (int r = 0; r < 4; r++) acc[i][j][r] = 0.f;

    for (int k0 = 0; k0 < K; k0 += BK) {
        // Load A tile (BM x BK) -> As[k][m], tf32-converted
#pragma unroll
        for (int l = 0; l < 2; l++) {
            int idx = tid + l * 256;          // float4 index, 512 total
            int row = idx >> 2;               // m: 0..127
            int kc  = (idx & 3) * 4;          // k: 0,4,8,12
            float4 a4 = *(const float4*)&Ap[(size_t)(m0 + row) * K + k0 + kc];
            As[kc + 0][row] = __uint_as_float(f2tf32(a4.x));
            As[kc + 1][row] = __uint_as_float(f2tf32(a4.y));
            As[kc + 2][row] = __uint_as_float(f2tf32(a4.z));
            As[kc + 3][row] = __uint_as_float(f2tf32(a4.w));
        }
        // Load B tile (BK x BN) -> Bs[k][n], tf32-converted
#pragma unroll
        for (int l = 0; l < 2; l++) {
            int idx = tid + l * 256;
            int kr  = idx >> 5;               // k: 0..15
            int nc  = (idx & 31) * 4;         // n: 0..124
            float4 b4 = *(const float4*)&B[(size_t)(k0 + kr) * N + n0 + nc];
            Bs[kr][nc + 0] = __uint_as_float(f2tf32(b4.x));
            Bs[kr][nc + 1] = __uint_as_float(f2tf32(b4.y));
            Bs[kr][nc + 2] = __uint_as_float(f2tf32(b4.z));
            Bs[kr][nc + 3] = __uint_as_float(f2tf32(b4.w));
        }
        __syncthreads();

#pragma unroll
        for (int kk = 0; kk < BK; kk += 8) {
            uint32_t afrag[4][4];
#pragma unroll
            for (int mi = 0; mi < 4; mi++) {
                int mb = warp_m * 64 + mi * 16 + group;
                afrag[mi][0] = __float_as_uint(As[kk + tig    ][mb    ]);
                afrag[mi][1] = __float_as_uint(As[kk + tig    ][mb + 8]);
                afrag[mi][2] = __float_as_uint(As[kk + tig + 4][mb    ]);
                afrag[mi][3] = __float_as_uint(As[kk + tig + 4][mb + 8]);
            }
            uint32_t bfrag[4][2];
#pragma unroll
            for (int nj = 0; nj < 4; nj++) {
                int nb = warp_n * 32 + nj * 8 + group;
                bfrag[nj][0] = __float_as_uint(Bs[kk + tig    ][nb]);
                bfrag[nj][1] = __float_as_uint(Bs[kk + tig + 4][nb]);
            }
#pragma unroll
            for (int mi = 0; mi < 4; mi++)
#pragma unroll
                for (int nj = 0; nj < 4; nj++)
                    mma_tf32(acc[mi][nj], afrag[mi], bfrag[nj]);
        }
        __syncthreads();
    }

    // Epilogue. C fragment mapping (m16n8k8):
    //   c0:(g, 2t) c1:(g, 2t+1) c2:(g+8, 2t) c3:(g+8, 2t+1)
#pragma unroll
    for (int mi = 0; mi < 4; mi++) {
#pragma unroll
        for (int nj = 0; nj < 4; nj++) {
#pragma unroll
            for (int r = 0; r < 4; r++) {
                int m = m0 + warp_m * 64 + mi * 16 + group + ((r >= 2) ? 8 : 0);
                int n = n0 + warp_n * 32 + nj * 8 + tig * 2 + (r & 1);
                float val = acc[mi][nj][r] + bias[n];
                if (MODE == 0) {
                    int b_ = m >> 10;
                    int tt = m & 1023;
                    int sec = n / CDIM;
                    int rem = n - sec * CDIM;
                    int hh  = rem >> 6;
                    int dd  = rem & 63;
                    size_t dst = (((size_t)b_ * NHEAD + hh) * TSEQ + tt) * DHEAD + dd;
                    if (sec == 0) {
                        g_q[dst] = val * 0.125f;   // d^-0.5, d=64
                    } else if (sec == 1) {
                        float rr = (tt > 0) ? rel_emb[(size_t)(tt - 1) * DHEAD + dd] : 0.f;
                        g_k[dst] = val + rr;
                    } else {
                        g_v[dst] = val;
                    }
                } else {
                    out[(size_t)m * CDIM + n] = val;
                }
            }
        }
    }
}

// ---------------------------------------------------------------------------
// Causal flash attention, fp32. One block = one (b,h) x 64-query tile.
// BQ=64, BKV=32, 256 threads (8 warps). Online softmax; rel folded into K.
// Writes y in [B, T, H, D] layout (row-major [8192, 768]) for proj GEMM.
// ---------------------------------------------------------------------------
__global__ __launch_bounds__(256)
void attn_kernel()
{
    const int BQ = 64, BKV = 32;

    __shared__ __align__(16) float Qs[DHEAD][BQ + 1];    // [64][65]
    __shared__ __align__(16) float Ks[DHEAD][BKV + 1];   // [64][33]
    __shared__ __align__(16) float Vs[BKV][DHEAD + 4];   // [32][68]
    __shared__ __align__(16) float Ps[BKV][BQ + 1];      // [32][65] (P^T)
    __shared__ float alpha_s[BQ];
    __shared__ float lbuf[BQ];

    const int tid  = threadIdx.x;
    const int warp = tid >> 5;
    const int lane = tid & 31;
    const int bh   = blockIdx.y;
    const int b_   = bh / NHEAD;
    const int h_   = bh % NHEAD;
    const int q0   = blockIdx.x * BQ;

    const float* qptr = g_q + (size_t)bh * TSEQ * DHEAD;
    const float* kptr = g_k + (size_t)bh * TSEQ * DHEAD;
    const float* vptr = g_v + (size_t)bh * TSEQ * DHEAD;

    // Load Q tile -> Qs[d][i]
    {
        int d = tid & 63;
        int ib = tid >> 6;   // 0..3
#pragma unroll
        for (int rep = 0; rep < 16; rep++) {
            int i = rep * 4 + ib;
            Qs[d][i] = qptr[(size_t)(q0 + i) * DHEAD + d];
        }
    }

    float m_r[8], l_r[8];
#pragma unroll
    for (int r = 0; r < 8; r++) { m_r[r] = -CUDART_INF_F; l_r[r] = 0.f; }

    float o[4][4];
#pragma unroll
    for (int i = 0; i < 4; i++)
#pragma unroll
        for (int j = 0; j < 4; j++) o[i][j] = 0.f;

    const int ti  = tid >> 4;   // 0..15: rows ti*4 .. ti*4+3
    const int tjS = tid & 15;   // 0..15: S cols tjS*2, tjS*2+1
    const int tjO = tid & 15;   // 0..15: O cols tjO*4 .. +3

    const int nkv = (q0 + BQ) / BKV;   // 2*qtile + 2

    for (int it = 0; it < nkv; it++) {
        const int kv0 = it * BKV;

        // Load K,V tiles
        {
            int d  = tid & 63;
            int jb = tid >> 6;   // 0..3
#pragma unroll
            for (int rep = 0; rep < 8; rep++) {
                int j = rep * 4 + jb;
                float kvv = kptr[(size_t)(kv0 + j) * DHEAD + d];
                float vvv = vptr[(size_t)(kv0 + j) * DHEAD + d];
                Ks[d][j] = kvv;
                Vs[j][d] = vvv;
            }
        }
        __syncthreads();

        // S = Q K^T  (64 x 32), 4x2 per thread
        float s[4][2];
#pragma unroll
        for (int i = 0; i < 4; i++) { s[i][0] = 0.f; s[i][1] = 0.f; }
#pragma unroll
        for (int d = 0; d < DHEAD; d++) {
            float a0 = Qs[d][ti * 4 + 0];
            float a1 = Qs[d][ti * 4 + 1];
            float a2 = Qs[d][ti * 4 + 2];
            float a3 = Qs[d][ti * 4 + 3];
            float b0 = Ks[d][tjS * 2 + 0];
            float b1 = Ks[d][tjS * 2 + 1];
            s[0][0] = fmaf(a0, b0, s[0][0]); s[0][1] = fmaf(a0, b1, s[0][1]);
            s[1][0] = fmaf(a1, b0, s[1][0]); s[1][1] = fmaf(a1, b1, s[1][1]);
            s[2][0] = fmaf(a2, b0, s[2][0]); s[2][1] = fmaf(a2, b1, s[2][1]);
            s[3][0] = fmaf(a3, b0, s[3][0]); s[3][1] = fmaf(a3, b1, s[3][1]);
        }

        const bool need_mask = (kv0 + BKV - 1 > q0);
#pragma unroll
        for (int i = 0; i < 4; i++) {
            int ig = q0 + ti * 4 + i;
#pragma unroll
            for (int j = 0; j < 2; j++) {
                int jg = kv0 + tjS * 2 + j;
                float vS = s[i][j];
                if (need_mask && jg > ig) vS = -1e30f;
                Ps[tjS * 2 + j][ti * 4 + i] = vS;
            }
        }
        __syncthreads();

        // Online softmax: warp w owns rows w*8 .. w*8+7; lane = kv column
#pragma unroll
        for (int r = 0; r < 8; r++) {
            int i = warp * 8 + r;
            float vv = Ps[lane][i];
            float mx = vv;
#pragma unroll
            for (int off = 16; off > 0; off >>= 1)
                mx = fmaxf(mx, __shfl_xor_sync(0xffffffffu, mx, off));
            float mnew = fmaxf(m_r[r], mx);
            float p = __expf(vv - mnew);
            float sum = p;
#pragma unroll
            for (int off = 16; off > 0; off >>= 1)
                sum += __shfl_xor_sync(0xffffffffu, sum, off);
            float al = __expf(m_r[r] - mnew);
            l_r[r] = l_r[r] * al + sum;
            m_r[r] = mnew;
            Ps[lane][i] = p;
            if (lane == 0) alpha_s[i] = al;
        }
        __syncthreads();

        // O = O*alpha + P V  (64 x 64), 4x4 per thread
        float al4[4];
#pragma unroll
        for (int i = 0; i < 4; i++) al4[i] = alpha_s[ti * 4 + i];
#pragma unroll
        for (int i = 0; i < 4; i++)
#pragma unroll
            for (int j = 0; j < 4; j++) o[i][j] *= al4[i];

#pragma unroll
        for (int j = 0; j < BKV; j++) {
            float p0 = Ps[j][ti * 4 + 0];
            float p1 = Ps[j][ti * 4 + 1];
            float p2 = Ps[j][ti * 4 + 2];
            float p3 = Ps[j][ti * 4 + 3];
            float4 vv = *(const float4*)&Vs[j][tjO * 4];
            o[0][0] = fmaf(p0, vv.x, o[0][0]); o[0][1] = fmaf(p0, vv.y, o[0][1]);
            o[0][2] = fmaf(p0, vv.z, o[0][2]); o[0][3] = fmaf(p0, vv.w, o[0][3]);
            o[1][0] = fmaf(p1, vv.x, o[1][0]); o[1][1] = fmaf(p1, vv.y, o[1][1]);
            o[1][2] = fmaf(p1, vv.z, o[1][2]); o[1][3] = fmaf(p1, vv.w, o[1][3]);
            o[2][0] = fmaf(p2, vv.x, o[2][0]); o[2][1] = fmaf(p2, vv.y, o[2][1]);
            o[2][2] = fmaf(p2, vv.z, o[2][2]); o[2][3] = fmaf(p2, vv.w, o[2][3]);
            o[3][0] = fmaf(p3, vv.x, o[3][0]); o[3][1] = fmaf(p3, vv.y, o[3][1]);
            o[3][2] = fmaf(p3, vv.z, o[3][2]); o[3][3] = fmaf(p3, vv.w, o[3][3]);
        }
        __syncthreads();
    }

    // Final l, write y[b][t][h*64+dd]
    if (lane == 0) {
#pragma unroll
        for (int r = 0; r < 8; r++) lbuf[warp * 8 + r] = l_r[r];
    }
    __syncthreads();

#pragma unroll
    for (int i = 0; i < 4; i++) {
        float inv = 1.f / lbuf[ti * 4 + i];
        int trow = q0 + ti * 4 + i;
        float4 ov;
        ov.x = o[i][0] * inv;
        ov.y = o[i][1] * inv;
        ov.z = o[i][2] * inv;
        ov.w = o[i][3] * inv;
        *(float4*)&g_y[((size_t)(b_ * TSEQ + trow)) * CDIM + h_ * DHEAD + tjO * 4] = ov;
    }
}

// ---------------------------------------------------------------------------
extern "C" void kernel_launch(void* const* d_in, const int* in_sizes, int n_in,
                              void* d_out, int out_size)
{
    const float* x       = (const float*)d_in[0];
    const float* w_attn  = (const float*)d_in[1];
    const float* b_attn  = (const float*)d_in[2];
    const float* w_proj  = (const float*)d_in[3];
    const float* b_proj  = (const float*)d_in[4];
    const float* rel_emb = (const float*)d_in[5];
    float* out = (float*)d_out;

    // 1) QKV GEMM + fused epilogue (scale q, fold rel into k)
    {
        dim3 grid(QKVN / 128, (BATCH * TSEQ) / 128);   // (18, 64)
        gemm_kernel<0><<<grid, 256>>>(x, w_attn, b_attn, rel_emb, nullptr, QKVN);
    }

    // 2) Causal flash attention
    {
        dim3 grid(TSEQ / 64, BATCH * NHEAD);           // (16, 96)
        attn_kernel<<<grid, 256>>>();
    }

    // 3) Output projection
    {
        dim3 grid(CDIM / 128, (BATCH * TSEQ) / 128);   // (6, 64)
        gemm_kernel<1><<<grid, 256>>>(nullptr, w_proj, b_proj, nullptr, out, CDIM);
    }
}

// round 4
// speedup vs baseline: 1.8178x; 1.8178x over previous
#include <cuda_runtime.h>
#include <math_constants.h>
#include <cstdint>

// Problem constants
#define BATCH   8
#define TSEQ    1024
#define CDIM    768
#define NHEAD   12
#define DHEAD   64
#define QKVN    (3 * CDIM)   // 2304

// Scratch (device globals: allocation-free rule)
__device__ float g_q[(size_t)BATCH * NHEAD * TSEQ * DHEAD];
__device__ float g_k[(size_t)BATCH * NHEAD * TSEQ * DHEAD];
__device__ float g_v[(size_t)BATCH * NHEAD * TSEQ * DHEAD];
__device__ float g_y[(size_t)BATCH * TSEQ * CDIM];

__device__ __forceinline__ uint32_t f2tf32(float f) {
    uint32_t r;
    asm("cvt.rna.tf32.f32 %0, %1;" : "=r"(r) : "f"(f));
    return r;
}
__device__ __forceinline__ float f2tf32f(float f) {
    return __uint_as_float(f2tf32(f));
}

__device__ __forceinline__ void mma_tf32(float c[4], const uint32_t a[4], const uint32_t b[2]) {
    asm volatile(
        "mma.sync.aligned.m16n8k8.row.col.f32.tf32.tf32.f32 "
        "{%0,%1,%2,%3}, {%4,%5,%6,%7}, {%8,%9}, {%0,%1,%2,%3};"
        : "+f"(c[0]), "+f"(c[1]), "+f"(c[2]), "+f"(c[3])
        : "r"(a[0]), "r"(a[1]), "r"(a[2]), "r"(a[3]),
          "r"(b[0]), "r"(b[1]));
}

// ---------------------------------------------------------------------------
// tf32 tensor-core GEMM: C[M,N] = A[M,K]*B[K,N] + bias, fused epilogue.
// MODE 0 (QKV): splits q/k/v, scales q, folds shifted rel_emb into k.
// MODE 1 (PROJ): A = g_y, B = w_proj -> out.
// ---------------------------------------------------------------------------
template <int MODE>
__global__ __launch_bounds__(256)
void gemm_kernel(const float* __restrict__ A,
                 const float* __restrict__ B,
                 const float* __restrict__ bias,
                 const float* __restrict__ rel_emb,
                 float* __restrict__ out,
                 int N)
{
    const int BM = 128, BK = 16;
    const int K = CDIM;
    const int LDS_ = 136;

    __shared__ __align__(16) float As[BK][LDS_];   // [k][m]
    __shared__ __align__(16) float Bs[BK][LDS_];   // [k][n]

    const int tid   = threadIdx.x;
    const int warp  = tid >> 5;
    const int lane  = tid & 31;
    const int group = lane >> 2;
    const int tig   = lane & 3;
    const int warp_m = warp >> 2;
    const int warp_n = warp & 3;
    const int m0 = blockIdx.y * BM;
    const int n0 = blockIdx.x * BM;

    const float* Ap = (MODE == 0) ? A : g_y;

    float acc[4][4][4];
#pragma unroll
    for (int i = 0; i < 4; i++)
#pragma unroll
        for (int j = 0; j < 4; j++)
#pragma unroll
            for (int r = 0; r < 4; r++) acc[i][j][r] = 0.f;

    for (int k0 = 0; k0 < K; k0 += BK) {
#pragma unroll
        for (int l = 0; l < 2; l++) {
            int idx = tid + l * 256;
            int row = idx >> 2;
            int kc  = (idx & 3) * 4;
            float4 a4 = *(const float4*)&Ap[(size_t)(m0 + row) * K + k0 + kc];
            As[kc + 0][row] = f2tf32f(a4.x);
            As[kc + 1][row] = f2tf32f(a4.y);
            As[kc + 2][row] = f2tf32f(a4.z);
            As[kc + 3][row] = f2tf32f(a4.w);
        }
#pragma unroll
        for (int l = 0; l < 2; l++) {
            int idx = tid + l * 256;
            int kr  = idx >> 5;
            int nc  = (idx & 31) * 4;
            float4 b4 = *(const float4*)&B[(size_t)(k0 + kr) * N + n0 + nc];
            Bs[kr][nc + 0] = f2tf32f(b4.x);
            Bs[kr][nc + 1] = f2tf32f(b4.y);
            Bs[kr][nc + 2] = f2tf32f(b4.z);
            Bs[kr][nc + 3] = f2tf32f(b4.w);
        }
        __syncthreads();

#pragma unroll
        for (int kk = 0; kk < BK; kk += 8) {
            uint32_t afrag[4][4];
#pragma unroll
            for (int mi = 0; mi < 4; mi++) {
                int mb = warp_m * 64 + mi * 16 + group;
                afrag[mi][0] = __float_as_uint(As[kk + tig    ][mb    ]);
                afrag[mi][1] = __float_as_uint(As[kk + tig    ][mb + 8]);
                afrag[mi][2] = __float_as_uint(As[kk + tig + 4][mb    ]);
                afrag[mi][3] = __float_as_uint(As[kk + tig + 4][mb + 8]);
            }
            uint32_t bfrag[4][2];
#pragma unroll
            for (int nj = 0; nj < 4; nj++) {
                int nb = warp_n * 32 + nj * 8 + group;
                bfrag[nj][0] = __float_as_uint(Bs[kk + tig    ][nb]);
                bfrag[nj][1] = __float_as_uint(Bs[kk + tig + 4][nb]);
            }
#pragma unroll
            for (int mi = 0; mi < 4; mi++)
#pragma unroll
                for (int nj = 0; nj < 4; nj++)
                    mma_tf32(acc[mi][nj], afrag[mi], bfrag[nj]);
        }
        __syncthreads();
    }

#pragma unroll
    for (int mi = 0; mi < 4; mi++) {
#pragma unroll
        for (int nj = 0; nj < 4; nj++) {
#pragma unroll
            for (int r = 0; r < 4; r++) {
                int m = m0 + warp_m * 64 + mi * 16 + group + ((r >= 2) ? 8 : 0);
                int n = n0 + warp_n * 32 + nj * 8 + tig * 2 + (r & 1);
                float val = acc[mi][nj][r] + bias[n];
                if (MODE == 0) {
                    int b_ = m >> 10;
                    int tt = m & 1023;
                    int sec = n / CDIM;
                    int rem = n - sec * CDIM;
                    int hh  = rem >> 6;
                    int dd  = rem & 63;
                    size_t dst = (((size_t)b_ * NHEAD + hh) * TSEQ + tt) * DHEAD + dd;
                    if (sec == 0) {
                        g_q[dst] = val * 0.125f;   // d^-0.5, d=64
                    } else if (sec == 1) {
                        float rr = (tt > 0) ? rel_emb[(size_t)(tt - 1) * DHEAD + dd] : 0.f;
                        g_k[dst] = val + rr;
                    } else {
                        g_v[dst] = val;
                    }
                } else {
                    out[(size_t)m * CDIM + n] = val;
                }
            }
        }
    }
}

// ---------------------------------------------------------------------------
// Causal flash attention on tf32 tensor cores.
// Block = 128 threads (4 warps), one (b,h) x 64-query tile. BKV = 64.
// Warp w owns S/O rows [16w, 16w+16). Q lives in registers as mma A-frags.
// K buffer and P buffer share smem (K dead once S computed).
// Smem strides: Ks/Ps 68 (conflict-free for their load patterns),
//               Vs 72 (conflict-free for PV B-frag loads).
// ---------------------------------------------------------------------------
__global__ __launch_bounds__(128)
void attn_kernel()
{
    const int SK = 68;   // Ks / Ps row stride (floats)
    const int SV = 72;   // Vs row stride

    __shared__ __align__(16) float KsPs[64 * SK];  // K tile, then P tile
    __shared__ __align__(16) float Vs[64 * SV];

    const int tid   = threadIdx.x;
    const int warp  = tid >> 5;
    const int lane  = tid & 31;
    const int group = lane >> 2;
    const int tig   = lane & 3;
    const int bh    = blockIdx.y;
    const int b_    = bh / NHEAD;
    const int h_    = bh % NHEAD;
    const int qi    = gridDim.x - 1 - blockIdx.x;   // longest blocks first
    const int q0    = qi * 64;

    const float* qptr = g_q + (size_t)bh * TSEQ * DHEAD;
    const float* kptr = g_k + (size_t)bh * TSEQ * DHEAD;
    const float* vptr = g_v + (size_t)bh * TSEQ * DHEAD;

    // ---- Stage Q into smem, then lift to A-fragments (registers) ----
#pragma unroll
    for (int rep = 0; rep < 8; rep++) {
        int idx4 = tid + rep * 128;          // 1024 float4 = 64x64
        int row  = idx4 >> 4;
        int c4   = (idx4 & 15) * 4;
        float4 q4 = *(const float4*)&qptr[(size_t)(q0 + row) * DHEAD + c4];
        KsPs[row * SK + c4 + 0] = f2tf32f(q4.x);
        KsPs[row * SK + c4 + 1] = f2tf32f(q4.y);
        KsPs[row * SK + c4 + 2] = f2tf32f(q4.z);
        KsPs[row * SK + c4 + 3] = f2tf32f(q4.w);
    }
    __syncthreads();

    const int r0 = warp * 16 + group;   // local S/O row (lo)
    const int r1 = r0 + 8;              // local S/O row (hi)

    uint32_t qf[8][4];
#pragma unroll
    for (int ks = 0; ks < 8; ks++) {
        qf[ks][0] = __float_as_uint(KsPs[r0 * SK + ks * 8 + tig]);
        qf[ks][1] = __float_as_uint(KsPs[r1 * SK + ks * 8 + tig]);
        qf[ks][2] = __float_as_uint(KsPs[r0 * SK + ks * 8 + tig + 4]);
        qf[ks][3] = __float_as_uint(KsPs[r1 * SK + ks * 8 + tig + 4]);
    }
    __syncthreads();

    float o[8][4];
#pragma unroll
    for (int n = 0; n < 8; n++)
#pragma unroll
        for (int r = 0; r < 4; r++) o[n][r] = 0.f;
    float m0 = -CUDART_INF_F, m1 = -CUDART_INF_F, l0 = 0.f, l1 = 0.f;

    for (int it = 0; it <= qi; it++) {
        const int kv0 = it * 64;

        // ---- Load K -> KsPs[j][d], V -> Vs[j][d] (tf32) ----
#pragma unroll
        for (int rep = 0; rep < 8; rep++) {
            int idx4 = tid + rep * 128;
            int j    = idx4 >> 4;
            int c4   = (idx4 & 15) * 4;
            float4 k4 = *(const float4*)&kptr[(size_t)(kv0 + j) * DHEAD + c4];
            float4 v4 = *(const float4*)&vptr[(size_t)(kv0 + j) * DHEAD + c4];
            KsPs[j * SK + c4 + 0] = f2tf32f(k4.x);
            KsPs[j * SK + c4 + 1] = f2tf32f(k4.y);
            KsPs[j * SK + c4 + 2] = f2tf32f(k4.z);
            KsPs[j * SK + c4 + 3] = f2tf32f(k4.w);
            Vs[j * SV + c4 + 0] = f2tf32f(v4.x);
            Vs[j * SV + c4 + 1] = f2tf32f(v4.y);
            Vs[j * SV + c4 + 2] = f2tf32f(v4.z);
            Vs[j * SV + c4 + 3] = f2tf32f(v4.w);
        }
        __syncthreads();

        // ---- S = Q K^T : 16x64 per warp ----
        float sf[8][4];
#pragma unroll
        for (int n = 0; n < 8; n++)
#pragma unroll
            for (int r = 0; r < 4; r++) sf[n][r] = 0.f;

#pragma unroll
        for (int n = 0; n < 8; n++) {
#pragma unroll
            for (int ks = 0; ks < 8; ks++) {
                uint32_t bf[2];
                bf[0] = __float_as_uint(KsPs[(n * 8 + group) * SK + ks * 8 + tig]);
                bf[1] = __float_as_uint(KsPs[(n * 8 + group) * SK + ks * 8 + tig + 4]);
                mma_tf32(sf[n], qf[ks], bf);
            }
        }

        // ---- Causal mask (diagonal tile only) ----
        if (it == qi) {
#pragma unroll
            for (int n = 0; n < 8; n++) {
#pragma unroll
                for (int r = 0; r < 4; r++) {
                    int jl = n * 8 + tig * 2 + (r & 1);
                    int il = (r >= 2) ? r1 : r0;
                    if (jl > il) sf[n][r] = -1e30f;
                }
            }
        }

        // ---- Online softmax (rows r0, r1 per thread; quad reduction) ----
        float mx0 = -CUDART_INF_F, mx1 = -CUDART_INF_F;
#pragma unroll
        for (int n = 0; n < 8; n++) {
            mx0 = fmaxf(mx0, fmaxf(sf[n][0], sf[n][1]));
            mx1 = fmaxf(mx1, fmaxf(sf[n][2], sf[n][3]));
        }
        mx0 = fmaxf(mx0, __shfl_xor_sync(0xffffffffu, mx0, 1));
        mx0 = fmaxf(mx0, __shfl_xor_sync(0xffffffffu, mx0, 2));
        mx1 = fmaxf(mx1, __shfl_xor_sync(0xffffffffu, mx1, 1));
        mx1 = fmaxf(mx1, __shfl_xor_sync(0xffffffffu, mx1, 2));

        float nm0 = fmaxf(m0, mx0);
        float nm1 = fmaxf(m1, mx1);
        float sum0 = 0.f, sum1 = 0.f;
#pragma unroll
        for (int n = 0; n < 8; n++) {
            sf[n][0] = __expf(sf[n][0] - nm0);
            sf[n][1] = __expf(sf[n][1] - nm0);
            sf[n][2] = __expf(sf[n][2] - nm1);
            sf[n][3] = __expf(sf[n][3] - nm1);
            sum0 += sf[n][0] + sf[n][1];
            sum1 += sf[n][2] + sf[n][3];
        }
        sum0 += __shfl_xor_sync(0xffffffffu, sum0, 1);
        sum0 += __shfl_xor_sync(0xffffffffu, sum0, 2);
        sum1 += __shfl_xor_sync(0xffffffffu, sum1, 1);
        sum1 += __shfl_xor_sync(0xffffffffu, sum1, 2);

        float a0 = __expf(m0 - nm0);
        float a1 = __expf(m1 - nm1);
        l0 = l0 * a0 + sum0;  m0 = nm0;
        l1 = l1 * a1 + sum1;  m1 = nm1;
#pragma unroll
        for (int n = 0; n < 8; n++) {
            o[n][0] *= a0; o[n][1] *= a0;
            o[n][2] *= a1; o[n][3] *= a1;
        }

        // ---- Release K buffer, store P (tf32) into same smem ----
        __syncthreads();
#pragma unroll
        for (int n = 0; n < 8; n++) {
            float2 p01 = make_float2(f2tf32f(sf[n][0]), f2tf32f(sf[n][1]));
            float2 p23 = make_float2(f2tf32f(sf[n][2]), f2tf32f(sf[n][3]));
            *(float2*)&KsPs[r0 * SK + n * 8 + tig * 2] = p01;
            *(float2*)&KsPs[r1 * SK + n * 8 + tig * 2] = p23;
        }
        __syncwarp();   // each warp reads back only its own rows

        // ---- O += P V ----
#pragma unroll
        for (int ks = 0; ks < 8; ks++) {
            uint32_t af[4];
            af[0] = __float_as_uint(KsPs[r0 * SK + ks * 8 + tig]);
            af[1] = __float_as_uint(KsPs[r1 * SK + ks * 8 + tig]);
            af[2] = __float_as_uint(KsPs[r0 * SK + ks * 8 + tig + 4]);
            af[3] = __float_as_uint(KsPs[r1 * SK + ks * 8 + tig + 4]);
#pragma unroll
            for (int n = 0; n < 8; n++) {
                uint32_t bf[2];
                bf[0] = __float_as_uint(Vs[(ks * 8 + tig    ) * SV + n * 8 + group]);
                bf[1] = __float_as_uint(Vs[(ks * 8 + tig + 4) * SV + n * 8 + group]);
                mma_tf32(o[n], af, bf);
            }
        }
        __syncthreads();   // protect KsPs/Vs before next tile's load
    }

    // ---- Normalize and write y[b][t][h*64+dd] ----
    float inv0 = 1.f / l0;
    float inv1 = 1.f / l1;
    size_t row_g0 = (size_t)(b_ * TSEQ + q0 + r0) * CDIM + h_ * DHEAD;
    size_t row_g1 = (size_t)(b_ * TSEQ + q0 + r1) * CDIM + h_ * DHEAD;
#pragma unroll
    for (int n = 0; n < 8; n++) {
        int cc = n * 8 + tig * 2;
        *(float2*)&g_y[row_g0 + cc] = make_float2(o[n][0] * inv0, o[n][1] * inv0);
        *(float2*)&g_y[row_g1 + cc] = make_float2(o[n][2] * inv1, o[n][3] * inv1);
    }
}

// ---------------------------------------------------------------------------
extern "C" void kernel_launch(void* const* d_in, const int* in_sizes, int n_in,
                              void* d_out, int out_size)
{
    const float* x       = (const float*)d_in[0];
    const float* w_attn  = (const float*)d_in[1];
    const float* b_attn  = (const float*)d_in[2];
    const float* w_proj  = (const float*)d_in[3];
    const float* b_proj  = (const float*)d_in[4];
    const float* rel_emb = (const float*)d_in[5];
    float* out = (float*)d_out;

    // 1) QKV GEMM + fused epilogue (scale q, fold rel into k)
    {
        dim3 grid(QKVN / 128, (BATCH * TSEQ) / 128);   // (18, 64)
        gemm_kernel<0><<<grid, 256>>>(x, w_attn, b_attn, rel_emb, nullptr, QKVN);
    }

    // 2) Causal flash attention (tf32 tensor cores)
    {
        dim3 grid(TSEQ / 64, BATCH * NHEAD);           // (16, 96)
        attn_kernel<<<grid, 128>>>();
    }

    // 3) Output projection
    {
        dim3 grid(CDIM / 128, (BATCH * TSEQ) / 128);   // (6, 64)
        gemm_kernel<1><<<grid, 256>>>(nullptr, w_proj, b_proj, nullptr, out, CDIM);
    }
}